// round 9
// baseline (speedup 1.0000x reference)
#include <cuda_runtime.h>
#include <cuda_bf16.h>

#define NPTS 1024
#define NG   27
#define NM   128
#define CUT2 25.0f
#define FULL 0xffffffffu
#define PPB  4

// Pair-centric minimal-image, shared-staged output. 4 points/block,
// 4 warps/point (512 thr, grid=256).
//  P1: each thread evaluates 8 pairs; only the nearest image can hit
//      (cutoff < box/2). Hits set bits in per-cell 1024-bit masks
//      (shared atomicOr) + per-cell counts (shared atomicAdd).
//  scan: 27-elem exclusive prefix -> exact argwhere offsets.
//  P2: lane l owns mask word pb=l; shfl exclusive scan + ffs emit into a
//      SHARED output row pre-filled with pad values.
//  flush: both rows written to global as coalesced float4 stores.
// OUTPUT FLOAT32: [1024*128] neigh | [1024*128*3] cells | [1] actual_max
__global__ __launch_bounds__(512) void periodic_neigh_kernel(
    const float* __restrict__ pos,     // (1024,3)
    const float* __restrict__ gp,      // (27,3) grid_points (== 20*cl)
    const int*   __restrict__ cl,      // (27,3) cell_list
    float* __restrict__ out)
{
    __shared__ float4   s4[NPTS];                 // 16 KB positions
    __shared__ float    clxf[NG], clyf[NG], clzf[NG];
    __shared__ unsigned smask[PPB][NG * 32];      // 13.5 KB
    __shared__ int      scnt[PPB][NG];
    __shared__ int      soff[PPB][NG + 1];
    __shared__ int      lut[NG];                  // shift(+1) base-3 -> g
    __shared__ __align__(16) float sneigh[PPB][NM];       // 2 KB
    __shared__ __align__(16) float scell[PPB][NM * 3];    // 6 KB

    const int tid  = threadIdx.x;
    const int lane = tid & 31;
    const int warp = tid >> 5;
    const int pt   = warp >> 2;
    const int w    = warp & 3;
    const int t128 = tid & 127;
    const int i    = blockIdx.x * PPB + pt;
    (void)gp;

    // zero masks + counts
    for (int v = tid; v < PPB * NG * 32; v += 512) ((unsigned*)smask)[v] = 0u;
    if (tid < PPB * NG) ((int*)scnt)[tid] = 0;

    // stage positions as float4
    for (int p = tid; p < NPTS; p += 512)
        s4[p] = make_float4(pos[3 * p], pos[3 * p + 1], pos[3 * p + 2], 0.0f);

    // tables: cell values (float) + data-driven shift->g LUT
    if (tid < NG) {
        const int a = cl[3 * tid], b = cl[3 * tid + 1], c = cl[3 * tid + 2];
        clxf[tid] = (float)a; clyf[tid] = (float)b; clzf[tid] = (float)c;
        lut[(a + 1) * 9 + (b + 1) * 3 + (c + 1)] = tid;
    }
    __syncthreads();

    // pre-fill output rows with pad values:
    // neigh = -1; cells = cell_list[NG-1] (jnp.take(-1) wraps to the end)
    {
        const float fx = clxf[NG - 1], fy = clyf[NG - 1], fz = clzf[NG - 1];
        sneigh[pt][t128] = -1.0f;
        scell[pt][t128 * 3 + 0] = fx;
        scell[pt][t128 * 3 + 1] = fy;
        scell[pt][t128 * 3 + 2] = fz;
    }

    const float4 qi = s4[i];

    // ---- Phase 1: 8 pairs per thread, nearest-image test ----
    #pragma unroll
    for (int k = 0; k < 8; k++) {
        const int p  = k * 128 + t128;
        const int pb = p >> 5;
        const float4 q = s4[p];
        const float sxf = rintf((q.x - qi.x) * 0.05f);   // exact in {-1,0,1}
        const float syf = rintf((q.y - qi.y) * 0.05f);
        const float szf = rintf((q.z - qi.z) * 0.05f);
        // reference arithmetic: (gx + xp) - xi with gx = -20*s (exact)
        const float dx = (-20.0f * sxf + q.x) - qi.x;
        const float dy = (-20.0f * syf + q.y) - qi.y;
        const float dz = (-20.0f * szf + q.z) - qi.z;
        const float d2 = dx * dx + dy * dy + dz * dz;
        if (d2 < CUT2) {
            const int idx = (int)(13.0f - (sxf * 9.0f + syf * 3.0f + szf));
            const int g = lut[idx];
            atomicOr(&smask[pt][(g << 5) + pb], 1u << lane);
            atomicAdd(&scnt[pt][g], 1);
        }
    }
    __syncthreads();

    // ---- exclusive scan over cells (warp 0 of each point) ----
    if (w == 0) {
        int v = (lane < NG) ? scnt[pt][lane] : 0;
        #pragma unroll
        for (int d = 1; d < 32; d <<= 1) {
            const int n = __shfl_up_sync(FULL, v, d);
            if (lane >= d) v += n;
        }
        if (lane < NG) soff[pt][lane + 1] = v;
        if (lane == 0) soff[pt][0] = 0;
    }
    __syncthreads();

    const int total = soff[pt][NG];

    // ---- Phase 2: lane l owns pb=l; shfl scan -> base; ffs emit to SMEM ----
    for (int g = w; g < NG; g += 4) {
        if (scnt[pt][g] == 0) continue;
        const int base = soff[pt][g];
        if (base >= NM) continue;
        unsigned m = smask[pt][(g << 5) + lane];
        const int c = __popc(m);
        int v = c;
        #pragma unroll
        for (int d = 1; d < 32; d <<= 1) {
            const int n = __shfl_up_sync(FULL, v, d);
            if (lane >= d) v += n;
        }
        int slot = base + v - c;                  // exclusive prefix
        if (m && slot < NM) {
            const float cx = clxf[g], cy = clyf[g], cz = clzf[g];
            const int pbase = lane * 32;
            do {
                const int b = __ffs(m) - 1;
                m &= m - 1;
                sneigh[pt][slot] = (float)(pbase + b);
                scell[pt][slot * 3 + 0] = cx;
                scell[pt][slot * 3 + 1] = cy;
                scell[pt][slot * 3 + 2] = cz;
                slot++;
            } while (m && slot < NM);
        }
    }
    __syncthreads();

    // ---- flush: coalesced float4 stores ----
    float4* __restrict__ neigh4 = (float4*)out;                  // 1024*32
    float4* __restrict__ cell4  = (float4*)(out + NPTS * NM);    // 1024*96
    float*  __restrict__ amax   = out + NPTS * NM * 4;

    if (t128 < NM / 4)
        neigh4[i * (NM / 4) + t128] = ((const float4*)sneigh[pt])[t128];
    if (t128 < (NM * 3) / 4)
        cell4[i * ((NM * 3) / 4) + t128] = ((const float4*)scell[pt])[t128];

    // actual_max (untruncated); int-view atomicMax == float max for
    // non-negative floats; poison 0xAAAAAAAA is negative and always loses.
    if (t128 == 0)
        atomicMax((int*)amax, __float_as_int((float)total));
}

extern "C" void kernel_launch(void* const* d_in, const int* in_sizes, int n_in,
                              void* d_out, int out_size) {
    const float* positions   = (const float*)d_in[0];
    const float* grid_points = (const float*)d_in[1];
    const int*   cell_list   = (const int*)d_in[2];
    (void)in_sizes; (void)n_in; (void)out_size;

    periodic_neigh_kernel<<<NPTS / PPB, 512>>>(positions, grid_points,
                                               cell_list, (float*)d_out);
}